// round 2
// baseline (speedup 1.0000x reference)
#include <cuda_runtime.h>

// Layout constants (fixed by the problem):
//   prediction:      [B=32, C=4, H=512, W=512] f32
//   intervals_comp_*:[B, C, N=64, 2, 2] i32
// Loss collapses to: 14.0 + sum_i w(comp,c,n) * (birth-death)^2
//   w_good = -0.0625/g, w_bad = +0.0625/(64-g), g = GOOD_comp[c]
// GOOD_0 = {1,2,1,3} packed as nibbles 0x3121
// GOOD_1 = {1,0,2,1} packed as nibbles 0x1201

#define NBC 128   // B*C blocks

__device__ float g_partials[NBC];

__global__ void __launch_bounds__(128, 1)
bd_partial_kernel(const float* __restrict__ pred,
                  const int*   __restrict__ iv0,
                  const int*   __restrict__ iv1)
{
    const int bc   = blockIdx.x;      // b*4 + c
    const int c    = bc & 3;
    const int tid  = threadIdx.x;     // 0..127
    const int comp = tid >> 6;        // 0 or 1
    const int n    = tid & 63;        // interval index

    const int* iv = comp ? iv1 : iv0;
    // One interval = 4 ints = 16 bytes, naturally aligned -> int4 load.
    const int4 co = reinterpret_cast<const int4*>(iv)[bc * 64 + n];

    const float* p = pred + (size_t)bc * (512 * 512);
    const float birth = __ldg(p + ((co.x << 9) | co.y));   // H,W = 512 -> shift/or
    const float death = __ldg(p + ((co.z << 9) | co.w));
    const float d = birth - death;

    // good-interval count for this (comp, class)
    const unsigned packed = comp ? 0x1201u : 0x3121u;
    const int g = (packed >> (c * 4)) & 0xF;

    // n < g is never true when g == 0, so the bad branch covers g==0 safely.
    const float w = (n < g) ? (-0.0625f / (float)g)
                            : ( 0.0625f / (float)(64 - g));
    float v = w * d * d;

    // Block reduction: warp shuffle, then 4 partials through smem.
    #pragma unroll
    for (int off = 16; off > 0; off >>= 1)
        v += __shfl_down_sync(0xFFFFFFFFu, v, off);

    __shared__ float s[4];
    if ((tid & 31) == 0) s[tid >> 5] = v;
    __syncthreads();
    if (tid == 0)
        g_partials[bc] = s[0] + s[1] + s[2] + s[3];
}

__global__ void __launch_bounds__(128, 1)
bd_finalize_kernel(float* __restrict__ out)
{
    const int tid = threadIdx.x;      // 0..127
    float v = g_partials[tid];

    #pragma unroll
    for (int off = 16; off > 0; off >>= 1)
        v += __shfl_down_sync(0xFFFFFFFFu, v, off);

    __shared__ float s[4];
    if ((tid & 31) == 0) s[tid >> 5] = v;
    __syncthreads();
    if (tid == 0)
        out[0] = s[0] + s[1] + s[2] + s[3] + 14.0f;
}

extern "C" void kernel_launch(void* const* d_in, const int* in_sizes, int n_in,
                              void* d_out, int out_size)
{
    const float* pred = (const float*)d_in[0];
    const int*   iv0  = (const int*)d_in[1];
    const int*   iv1  = (const int*)d_in[2];
    float* out = (float*)d_out;

    bd_partial_kernel<<<NBC, 128>>>(pred, iv0, iv1);
    bd_finalize_kernel<<<1, 128>>>(out);
}